// round 5
// baseline (speedup 1.0000x reference)
#include <cuda_runtime.h>
#include <cstdint>

// CenterLoss collapses: mask is one-hot per row, clip() lifts the masked-out
// zeros to exactly 1e-12, so
//   loss = (1/B) * sum_b clamp(||x_b - c_{label_b}||^2, 1e-12, 1e12)
//          + (NUM_CLASSES - 1) * 1e-12
// 16.8 MB of gathered reads, single fused kernel with last-block-done final
// reduction. R5: sample split across 2 warps to double occupancy (43% -> ~86%)
// and outstanding-load count — R4 profile showed latency-bound (DRAM 21%).

#define CL_BATCH           4096
#define CL_DIM             512
#define CL_NUM_CLASSES     10000
#define CL_THREADS         256
#define CL_SAMPLES_PER_BLK 4                       // 2 warps per sample
#define CL_NBLOCKS         (CL_BATCH / CL_SAMPLES_PER_BLK)   // 1024

__device__ float        g_cl_partials[CL_NBLOCKS];
__device__ unsigned int g_cl_count = 0;

// Labels may be int64 or int32. For int64 (values < 10000) every odd 32-bit
// word is the zero high-half; for int32 the odd words are random labels.
// 8 odd words all-zero => int64 (misclassification prob ~1e-32).
__device__ __forceinline__ int cl_load_label(const int* __restrict__ lw, int b) {
    int or_acc = 0;
#pragma unroll
    for (int i = 0; i < 8; ++i) or_acc |= lw[2 * i + 1];
    return (or_acc == 0) ? lw[2 * b] : lw[b];
}

__global__ __launch_bounds__(CL_THREADS)
void centerloss_fused_kernel(const float* __restrict__ x,
                             const int* __restrict__ label_words,
                             const float* __restrict__ centers,
                             float* __restrict__ out) {
    const int warp = threadIdx.x >> 5;
    const int lane = threadIdx.x & 31;
    const int samp_in_blk = warp >> 1;          // 0..3
    const int half        = warp & 1;           // which 256-float half
    const int b = blockIdx.x * CL_SAMPLES_PER_BLK + samp_in_blk;

    int lbl = 0;
    if (lane == 0) lbl = cl_load_label(label_words, b);
    lbl = __shfl_sync(0xffffffffu, lbl, 0);

    // Each sample = 128 float4. This warp covers float4 indices
    // [half*64, half*64+64): lane and lane+32 within that range.
    const float4* __restrict__ xr =
        reinterpret_cast<const float4*>(x + (size_t)b * CL_DIM) + half * 64;
    const float4* __restrict__ cr =
        reinterpret_cast<const float4*>(centers + (size_t)lbl * CL_DIM) + half * 64;

    // Front-batch all 4 loads for max MLP.
    const float4 a0 = xr[lane];
    const float4 a1 = xr[lane + 32];
    const float4 c0 = cr[lane];
    const float4 c1 = cr[lane + 32];

    float acc;
    {
        float d;
        d = a0.x - c0.x; acc  = d * d;
        d = a0.y - c0.y; acc  = fmaf(d, d, acc);
        d = a0.z - c0.z; acc  = fmaf(d, d, acc);
        d = a0.w - c0.w; acc  = fmaf(d, d, acc);
        d = a1.x - c1.x; acc  = fmaf(d, d, acc);
        d = a1.y - c1.y; acc  = fmaf(d, d, acc);
        d = a1.z - c1.z; acc  = fmaf(d, d, acc);
        d = a1.w - c1.w; acc  = fmaf(d, d, acc);
    }

#pragma unroll
    for (int o = 16; o > 0; o >>= 1)
        acc += __shfl_xor_sync(0xffffffffu, acc, o);

    __shared__ float s[8];                      // one half-sum per warp
    if (lane == 0) s[warp] = acc;
    __syncthreads();

    // Block partial (thread 0): combine halves, clamp per sample, sum.
    __shared__ bool is_last;
    if (threadIdx.x == 0) {
        float t = 0.0f;
#pragma unroll
        for (int i = 0; i < CL_SAMPLES_PER_BLK; ++i) {
            const float dist = s[2 * i] + s[2 * i + 1];
            t += fminf(fmaxf(dist, 1e-12f), 1e12f);   // clip(dist, 1e-12, 1e12)
        }
        g_cl_partials[blockIdx.x] = t;
        __threadfence();
        // atomicInc wraps old==NBLOCKS-1 -> 0: auto-reset for graph replay.
        unsigned int prev = atomicInc(&g_cl_count, CL_NBLOCKS - 1);
        is_last = (prev == CL_NBLOCKS - 1);
    }
    __syncthreads();

    // Last block reduces all 1024 partials in double (fixed order).
    if (is_last) {
        __shared__ double sd[CL_THREADS];
        const int t = threadIdx.x;
        double v = 0.0;
#pragma unroll
        for (int i = 0; i < CL_NBLOCKS / CL_THREADS; ++i)
            v += (double)g_cl_partials[t + i * CL_THREADS];
        sd[t] = v;
        __syncthreads();
#pragma unroll
        for (int stride = CL_THREADS / 2; stride > 32; stride >>= 1) {
            if (t < stride) sd[t] += sd[t + stride];
            __syncthreads();
        }
        if (t < 32) {
            double w = sd[t] + sd[t + 32];
#pragma unroll
            for (int o = 16; o > 0; o >>= 1)
                w += __shfl_xor_sync(0xffffffffu, w, o);
            if (t == 0) {
                const double zeros_term = (double)(CL_NUM_CLASSES - 1) * 1e-12;
                out[0] = (float)(w / (double)CL_BATCH + zeros_term);
            }
        }
    }
}

extern "C" void kernel_launch(void* const* d_in, const int* in_sizes, int n_in,
                              void* d_out, int out_size) {
    // Identify inputs by unique element counts:
    //   x: 4096*512 = 2097152, centers: 10000*512 = 5120000, labels: 4096.
    const float* x       = nullptr;
    const float* centers = nullptr;
    const int*   labels  = nullptr;
    for (int i = 0; i < n_in; ++i) {
        if (in_sizes[i] == CL_BATCH * CL_DIM)            x       = (const float*)d_in[i];
        else if (in_sizes[i] == CL_NUM_CLASSES * CL_DIM) centers = (const float*)d_in[i];
        else if (in_sizes[i] == CL_BATCH)                labels  = (const int*)d_in[i];
    }
    if (!x)       x       = (const float*)d_in[0];
    if (!labels)  labels  = (const int*)d_in[1];
    if (!centers) centers = (const float*)d_in[2];

    centerloss_fused_kernel<<<CL_NBLOCKS, CL_THREADS>>>(
        x, labels, centers, (float*)d_out);
}